// round 12
// baseline (speedup 1.0000x reference)
#include <cuda_runtime.h>

namespace {
constexpr int kGroups   = 131072;                 // 64 * 2048
constexpr int kThreadsT = 2 * kGroups;            // 2 threads (halves) per group
constexpr int kThreads  = 256;
constexpr int kBlocks   = kThreadsT / kThreads;   // 1024
constexpr int kVecs     = kThreads * 6;           // 1536 float4 per block tile
constexpr float kDT  = 0.005f;
// fold loss32 denominator into lane weight: (64*1019*3*4) scale vs (64*2043*3)
constexpr float kC32 = (float)(392256.0 / 782592.0);
}

__device__ double g_partials[kBlocks];
__device__ unsigned int g_sync = 0;

__device__ __forceinline__ void qmul(float aw, float ax, float ay, float az,
                                     float bw, float bx, float by, float bz,
                                     float& w, float& x, float& y, float& z) {
    w = aw*bw - ax*bx - ay*by - az*bz;
    x = aw*bx + ax*bw + ay*bz - az*by;
    y = aw*by - ax*bz + ay*bw + az*bx;
    z = aw*bz + ax*by - ay*bx + az*bw;
}

// exp of phi = kDT * u as unit quaternion, |phi| <= ~0.2: even-poly, branch-free.
__device__ __forceinline__ void exp_quat_dt(float ux, float uy, float uz,
                                            float& w, float& x, float& y, float& z) {
    float n2 = fmaf(ux, ux, fmaf(uy, uy, uz * uz));
    float h2 = (0.25f * kDT * kDT) * n2;                    // (|phi|/2)^2
    w = fmaf(h2, fmaf(h2, (1.0f / 24.0f), -0.5f), 1.0f);
    float s = fmaf(h2, fmaf(h2, (kDT / 240.0f), -(kDT / 12.0f)), 0.5f * kDT);
    x = s * ux; y = s * uy; z = s * uz;                     // s = sin(h)/|u|
}

// atan2(n, w) for n >= 0, w >= 0 (result in [0, pi/2]); ~1e-7 rad
__device__ __forceinline__ float atan2_pos(float n, float w) {
    bool swap = n > w;
    float num = swap ? w : n;
    float den = swap ? n : w;
    float q  = __fdividef(num, den);              // [0, 1]
    float q2 = q * q;
    float p =                     -0.0040540580734172f;
    p = fmaf(p, q2,  0.0218612288251226f);
    p = fmaf(p, q2, -0.0559098861838105f);
    p = fmaf(p, q2,  0.0964200441046623f);
    p = fmaf(p, q2, -0.1390853351676372f);
    p = fmaf(p, q2,  0.1994653599057577f);
    p = fmaf(p, q2, -0.3332985605689738f);
    p = fmaf(p, q2,  0.9999993329093277f);
    float a = p * q;
    return swap ? (1.5707963267948966f - a) : a;
}

// rs = log( R(a)^T R(b) );  returns sum_k SmoothL1(rs_k / HUBER)
__device__ __forceinline__ float log_huber_q(float aw, float ax, float ay, float az,
                                             float bw, float bx, float by, float bz) {
    float w = aw*bw + ax*bx + ay*by + az*bz;      // conj(a) (x) b
    float x = aw*bx - ax*bw - ay*bz + az*by;
    float y = aw*by + ax*bz - ay*bw - az*bx;
    float z = aw*bz - ax*by + ay*bx - az*bw;
    if (w < 0.0f) { w = -w; x = -x; y = -y; z = -z; }
    float n2 = fmaf(x, x, fmaf(y, y, z * z));
    float n  = sqrtf(n2);
    float ang = 2.0f * atan2_pos(n, w);           // [0, pi]
    float coef = __fdividef(ang, fmaxf(n, 1e-20f));
    float r0 = coef * x, r1 = coef * y, r2 = coef * z;

    float sum = 0.0f;
#pragma unroll
    for (int k = 0; k < 3; k++) {
        float r = (k == 0) ? r0 : ((k == 1) ? r1 : r2);
        float xx = r * 200.0f;                    // / HUBER
        float axv = fabsf(xx);
        sum += (axv < 1.0f) ? (0.5f * xx * xx) : (axv - 0.5f);
    }
    return sum;
}

__global__ void __launch_bounds__(kThreads)
dg_loss_kernel(const float* __restrict__ w_hat, const float* __restrict__ dw16,
               float* __restrict__ out) {
    __shared__ float4 tile[kVecs];                // raw block tile of w_hat (24 KB)

    const int tid  = threadIdx.x;
    const int t    = blockIdx.x * kThreads + tid;          // half-group id
    const int m    = t >> 1;                               // group id
    const int g    = m & 2047;                             // group index in row
    const int half = t & 1;
    const int lane = tid & 31;
    const bool mEven = (m & 1) == 0;

    // ---- dw16: ONE strided load per group (even lane of pair), broadcast ----
    float4 d = make_float4(0.f, 0.f, 0.f, 0.f);
    if (half == 0) d = __ldcs(reinterpret_cast<const float4*>(dw16) + (size_t)m * 12);
    {
        int src = lane & ~1;                               // even lane of the pair
        d.x = __shfl_sync(0xFFFFFFFFu, d.x, src);
        d.y = __shfl_sync(0xFFFFFFFFu, d.y, src);
        d.z = __shfl_sync(0xFFFFFFFFu, d.z, src);
    }

    // ---- phase 1: fully coalesced raw copy of w_hat tile into smem ----
    const float4* wbase = reinterpret_cast<const float4*>(w_hat)
                        + (size_t)blockIdx.x * kVecs;
#pragma unroll
    for (int it = 0; it < 6; it++) {
        int jl = it * kThreads + tid;                      // 0..1535
        tile[jl] = __ldcs(wbase + jl);
    }
    __syncthreads();

    // ---- phase 2: sum this half-group's 24 floats; component = i % 3 (24h % 3 == 0) ----
    float ux, uy, uz;
    {
        const float4* p = tile + 6 * tid;
        float4 q0 = p[0], q1 = p[1], q2 = p[2], q3 = p[3], q4 = p[4], q5 = p[5];
        ux = ((q0.x + q0.w) + (q1.z + q2.y)) + ((q3.x + q3.w) + (q4.z + q5.y));
        uy = ((q0.y + q1.x) + (q1.w + q2.z)) + ((q3.y + q4.x) + (q4.w + q5.z));
        uz = ((q0.z + q1.y) + (q2.x + q2.w)) + ((q3.z + q4.y) + (q5.x + q5.w));
    }

    // ---- combine halves (BCH: vector sums add); both lanes identical ----
    ux += __shfl_xor_sync(0xFFFFFFFFu, ux, 1);
    uy += __shfl_xor_sync(0xFFFFFFFFu, uy, 1);
    uz += __shfl_xor_sync(0xFFFFFFFFu, uz, 1);

    float qw, qx, qy, qz;
    exp_quat_dt(ux, uy, uz, qw, qx, qy, qz);      // qhat for group m

    // ---- ground-truth increment for group m (both lanes) ----
    float pw, px, py, pz;
    {
        float n2 = fmaf(d.x, d.x, fmaf(d.y, d.y, d.z * d.z));
        float th = sqrtf(n2);
        float s, c;
        __sincosf(0.5f * th, &s, &c);
        float k = (th > 1e-7f) ? __fdividef(s, th) : 0.5f;
        pw = c; px = k * d.x; py = k * d.y; pz = k * d.z;
    }

    // ---- exchange with partner group (m ^ 1): lanes t <-> t^2 ----
    float qwP = __shfl_xor_sync(0xFFFFFFFFu, qw, 2);
    float qxP = __shfl_xor_sync(0xFFFFFFFFu, qx, 2);
    float qyP = __shfl_xor_sync(0xFFFFFFFFu, qy, 2);
    float qzP = __shfl_xor_sync(0xFFFFFFFFu, qz, 2);
    float pwP = __shfl_xor_sync(0xFFFFFFFFu, pw, 2);
    float pxP = __shfl_xor_sync(0xFFFFFFFFu, px, 2);
    float pyP = __shfl_xor_sync(0xFFFFFFFFu, py, 2);
    float pzP = __shfl_xor_sync(0xFFFFFFFFu, pz, 2);

    // ---- branch-free lane specialization: partner or identity (exact) ----
    bool pair = (half == 1);
    float sw = pair ? qwP : 1.0f, sx = pair ? qxP : 0.0f,
          sy = pair ? qyP : 0.0f, sz = pair ? qzP : 0.0f;
    float tw = pair ? pwP : 1.0f, tx = pair ? pxP : 0.0f,
          ty = pair ? pyP : 0.0f, tz = pair ? pzP : 0.0f;
    float Aw, Ax, Ay, Az, Bw, Bx, By, Bz;
    qmul(qw, qx, qy, qz, sw, sx, sy, sz, Aw, Ax, Ay, Az);
    qmul(pw, px, py, pz, tw, tx, ty, tz, Bw, Bx, By, Bz);

    float val = log_huber_q(Aw, Ax, Ay, Az, Bw, Bx, By, Bz);

    // ---- single weighted accumulator ----
    bool valid = pair ? (mEven && g >= 10) : (g >= 5);
    float v = valid ? (pair ? val * kC32 : val) : 0.0f;

    // ---- deterministic block reduction ----
#pragma unroll
    for (int off = 16; off > 0; off >>= 1)
        v += __shfl_down_sync(0xFFFFFFFFu, v, off);
    __shared__ float warr[kThreads / 32];
    __shared__ double sa[kThreads];
    __shared__ bool isLast;
    int wid = tid >> 5;
    if (lane == 0) warr[wid] = v;
    __syncthreads();
    if (tid == 0) {
        float a = 0.0f;
#pragma unroll
        for (int i = 0; i < kThreads / 32; i++) a += warr[i];
        g_partials[blockIdx.x] = (double)a;
        __threadfence();
        unsigned prev = atomicAdd(&g_sync, 1u);
        isLast = (prev == (unsigned)(kBlocks - 1));
    }
    __syncthreads();

    // ---- last block: fixed-order final sum => deterministic ----
    if (isLast) {
        __threadfence();
        double a = 0.0;
#pragma unroll
        for (int j = 0; j < kBlocks / kThreads; j++)
            a += g_partials[tid + j * kThreads];
        sa[tid] = a;
        __syncthreads();
        for (int off = kThreads / 2; off > 0; off >>= 1) {
            if (tid < off) sa[tid] += sa[tid + off];
            __syncthreads();
        }
        if (tid == 0) {
            // loss = W*HUBER^2 * S / (64*2043*3);  s32 pre-scaled by kC32
            out[0] = (float)(25.0 * sa[0] / 392256.0);
            g_sync = 0;                          // reset for next graph replay
        }
    }
}

extern "C" void kernel_launch(void* const* d_in, const int* in_sizes, int n_in,
                              void* d_out, int out_size) {
    const float* w_hat = (const float*)d_in[0];
    const float* dw16  = (const float*)d_in[1];
    float* out = (float*)d_out;
    dg_loss_kernel<<<kBlocks, kThreads>>>(w_hat, dw16, out);
}

// round 13
// speedup vs baseline: 1.0307x; 1.0307x over previous
#include <cuda_runtime.h>

namespace {
constexpr int kGroups   = 131072;                 // 64 * 2048
constexpr int kThreadsT = 2 * kGroups;            // 2 threads (halves) per group
constexpr int kThreads  = 256;
constexpr int kBlocks   = kThreadsT / kThreads;   // 1024
constexpr int kVecs     = kThreads * 6;           // 1536 float4 per block tile
constexpr int kTileBytes = kVecs * 16;            // 24576
constexpr float kDT  = 0.005f;
constexpr float kC32 = (float)(392256.0 / 782592.0);  // fold loss32 denom into lane weight
}

__device__ double g_partials[kBlocks];
__device__ unsigned int g_sync = 0;

__device__ __forceinline__ unsigned smem_u32(const void* p) {
    unsigned a;
    asm("{ .reg .u64 t; cvta.to.shared.u64 t, %1; cvt.u32.u64 %0, t; }"
        : "=r"(a) : "l"(p));
    return a;
}

__device__ __forceinline__ void qmul(float aw, float ax, float ay, float az,
                                     float bw, float bx, float by, float bz,
                                     float& w, float& x, float& y, float& z) {
    w = aw*bw - ax*bx - ay*by - az*bz;
    x = aw*bx + ax*bw + ay*bz - az*by;
    y = aw*by - ax*bz + ay*bw + az*bx;
    z = aw*bz + ax*by - ay*bx + az*bw;
}

// exp of phi = kDT * u as unit quaternion, |phi| <= ~0.2: even-poly, branch-free.
__device__ __forceinline__ void exp_quat_dt(float ux, float uy, float uz,
                                            float& w, float& x, float& y, float& z) {
    float n2 = fmaf(ux, ux, fmaf(uy, uy, uz * uz));
    float h2 = (0.25f * kDT * kDT) * n2;                    // (|phi|/2)^2
    w = fmaf(h2, fmaf(h2, (1.0f / 24.0f), -0.5f), 1.0f);
    float s = fmaf(h2, fmaf(h2, (kDT / 240.0f), -(kDT / 12.0f)), 0.5f * kDT);
    x = s * ux; y = s * uy; z = s * uz;                     // s = sin(h)/|u|
}

// atan2(n, w) for n >= 0, w >= 0 (result in [0, pi/2]); ~1e-7 rad
__device__ __forceinline__ float atan2_pos(float n, float w) {
    bool swap = n > w;
    float num = swap ? w : n;
    float den = swap ? n : w;
    float q  = __fdividef(num, den);              // [0, 1]
    float q2 = q * q;
    float p =                     -0.0040540580734172f;
    p = fmaf(p, q2,  0.0218612288251226f);
    p = fmaf(p, q2, -0.0559098861838105f);
    p = fmaf(p, q2,  0.0964200441046623f);
    p = fmaf(p, q2, -0.1390853351676372f);
    p = fmaf(p, q2,  0.1994653599057577f);
    p = fmaf(p, q2, -0.3332985605689738f);
    p = fmaf(p, q2,  0.9999993329093277f);
    float a = p * q;
    return swap ? (1.5707963267948966f - a) : a;
}

// rs = log( R(a)^T R(b) );  returns sum_k SmoothL1(rs_k / HUBER)
__device__ __forceinline__ float log_huber_q(float aw, float ax, float ay, float az,
                                             float bw, float bx, float by, float bz) {
    float w = aw*bw + ax*bx + ay*by + az*bz;      // conj(a) (x) b
    float x = aw*bx - ax*bw - ay*bz + az*by;
    float y = aw*by + ax*bz - ay*bw - az*bx;
    float z = aw*bz - ax*by + ay*bx - az*bw;
    if (w < 0.0f) { w = -w; x = -x; y = -y; z = -z; }
    float n2 = fmaf(x, x, fmaf(y, y, z * z));
    float n  = sqrtf(n2);
    float ang = 2.0f * atan2_pos(n, w);           // [0, pi]
    float coef = __fdividef(ang, fmaxf(n, 1e-20f));
    float r0 = coef * x, r1 = coef * y, r2 = coef * z;

    float sum = 0.0f;
#pragma unroll
    for (int k = 0; k < 3; k++) {
        float r = (k == 0) ? r0 : ((k == 1) ? r1 : r2);
        float xx = r * 200.0f;                    // / HUBER
        float axv = fabsf(xx);
        sum += (axv < 1.0f) ? (0.5f * xx * xx) : (axv - 0.5f);
    }
    return sum;
}

__global__ void __launch_bounds__(kThreads, 8)
dg_loss_kernel(const float* __restrict__ w_hat, const float* __restrict__ dw16,
               float* __restrict__ out) {
    __shared__ alignas(128) float4 tile[kVecs];   // 24 KB raw w_hat tile
    __shared__ alignas(8) unsigned long long mbar;

    const int tid  = threadIdx.x;
    const int t    = blockIdx.x * kThreads + tid;          // half-group id
    const int m    = t >> 1;                               // group id
    const int g    = m & 2047;                             // group index in row
    const int half = t & 1;
    const int lane = tid & 31;
    const bool mEven = (m & 1) == 0;

    // ---- TMA bulk load of the whole tile: bypasses L1tex entirely ----
    const unsigned mb = smem_u32(&mbar);
    if (tid == 0) {
        asm volatile("mbarrier.init.shared.b64 [%0], %1;" :: "r"(mb), "r"(1) : "memory");
    }
    __syncthreads();
    if (tid == 0) {
        asm volatile("mbarrier.arrive.expect_tx.shared.b64 _, [%0], %1;"
                     :: "r"(mb), "r"((unsigned)kTileBytes) : "memory");
        const char* src = reinterpret_cast<const char*>(w_hat)
                        + (size_t)blockIdx.x * kTileBytes;
        asm volatile("cp.async.bulk.shared::cta.global.mbarrier::complete_tx::bytes "
                     "[%0], [%1], %2, [%3];"
                     :: "r"(smem_u32(tile)), "l"(src), "r"((unsigned)kTileBytes), "r"(mb)
                     : "memory");
    }

    // ---- overlap with the wait: dw16 (one strided load per group) + gt exp ----
    float4 d = make_float4(0.f, 0.f, 0.f, 0.f);
    if (half == 0) d = __ldcs(reinterpret_cast<const float4*>(dw16) + (size_t)m * 12);
    {
        int src = lane & ~1;                               // even lane of the pair
        d.x = __shfl_sync(0xFFFFFFFFu, d.x, src);
        d.y = __shfl_sync(0xFFFFFFFFu, d.y, src);
        d.z = __shfl_sync(0xFFFFFFFFu, d.z, src);
    }
    float pw, px, py, pz;
    {
        float n2 = fmaf(d.x, d.x, fmaf(d.y, d.y, d.z * d.z));
        float th = sqrtf(n2);
        float s, c;
        __sincosf(0.5f * th, &s, &c);
        float k = (th > 1e-7f) ? __fdividef(s, th) : 0.5f;
        pw = c; px = k * d.x; py = k * d.y; pz = k * d.z;
    }

    // ---- wait for the bulk copy (acquire: orders subsequent ld.shared) ----
    {
        unsigned done;
        asm volatile(
            "{\n\t.reg .pred p;\n\t"
            "mbarrier.try_wait.parity.acquire.cta.shared::cta.b64 p, [%1], %2;\n\t"
            "selp.b32 %0, 1, 0, p;\n\t}"
            : "=r"(done) : "r"(mb), "r"(0u) : "memory");
        if (!done) {
            asm volatile(
                "{\n\t.reg .pred P1;\n\t"
                "WL_%=:\n\t"
                "mbarrier.try_wait.parity.acquire.cta.shared::cta.b64 P1, [%0], %1, 0x989680;\n\t"
                "@P1 bra.uni WD_%=;\n\t"
                "bra.uni WL_%=;\n\t"
                "WD_%=:\n\t}"
                :: "r"(mb), "r"(0u) : "memory");
        }
    }

    // ---- phase 2: sum this half-group's 24 floats (BCH); component = i % 3 ----
    float ux, uy, uz;
    {
        const float4* p = tile + 6 * tid;
        float4 q0 = p[0], q1 = p[1], q2 = p[2], q3 = p[3], q4 = p[4], q5 = p[5];
        ux = ((q0.x + q0.w) + (q1.z + q2.y)) + ((q3.x + q3.w) + (q4.z + q5.y));
        uy = ((q0.y + q1.x) + (q1.w + q2.z)) + ((q3.y + q4.x) + (q4.w + q5.z));
        uz = ((q0.z + q1.y) + (q2.x + q2.w)) + ((q3.z + q4.y) + (q5.x + q5.w));
    }

    // ---- combine halves (BCH: vector sums add); both lanes identical ----
    ux += __shfl_xor_sync(0xFFFFFFFFu, ux, 1);
    uy += __shfl_xor_sync(0xFFFFFFFFu, uy, 1);
    uz += __shfl_xor_sync(0xFFFFFFFFu, uz, 1);

    float qw, qx, qy, qz;
    exp_quat_dt(ux, uy, uz, qw, qx, qy, qz);      // qhat for group m

    // ---- exchange with partner group (m ^ 1): lanes t <-> t^2 ----
    float qwP = __shfl_xor_sync(0xFFFFFFFFu, qw, 2);
    float qxP = __shfl_xor_sync(0xFFFFFFFFu, qx, 2);
    float qyP = __shfl_xor_sync(0xFFFFFFFFu, qy, 2);
    float qzP = __shfl_xor_sync(0xFFFFFFFFu, qz, 2);
    float pwP = __shfl_xor_sync(0xFFFFFFFFu, pw, 2);
    float pxP = __shfl_xor_sync(0xFFFFFFFFu, px, 2);
    float pyP = __shfl_xor_sync(0xFFFFFFFFu, py, 2);
    float pzP = __shfl_xor_sync(0xFFFFFFFFu, pz, 2);

    // ---- branch-free lane specialization: partner or identity (exact) ----
    bool pair = (half == 1);
    float sw = pair ? qwP : 1.0f, sx = pair ? qxP : 0.0f,
          sy = pair ? qyP : 0.0f, sz = pair ? qzP : 0.0f;
    float tw = pair ? pwP : 1.0f, tx = pair ? pxP : 0.0f,
          ty = pair ? pyP : 0.0f, tz = pair ? pzP : 0.0f;
    float Aw, Ax, Ay, Az, Bw, Bx, By, Bz;
    qmul(qw, qx, qy, qz, sw, sx, sy, sz, Aw, Ax, Ay, Az);
    qmul(pw, px, py, pz, tw, tx, ty, tz, Bw, Bx, By, Bz);

    float val = log_huber_q(Aw, Ax, Ay, Az, Bw, Bx, By, Bz);

    bool valid = pair ? (mEven && g >= 10) : (g >= 5);
    float v = valid ? (pair ? val * kC32 : val) : 0.0f;

    // ---- deterministic block reduction ----
#pragma unroll
    for (int off = 16; off > 0; off >>= 1)
        v += __shfl_down_sync(0xFFFFFFFFu, v, off);
    __shared__ float warr[kThreads / 32];
    __shared__ double sa[kThreads];
    __shared__ bool isLast;
    int wid = tid >> 5;
    if (lane == 0) warr[wid] = v;
    __syncthreads();
    if (tid == 0) {
        float a = 0.0f;
#pragma unroll
        for (int i = 0; i < kThreads / 32; i++) a += warr[i];
        g_partials[blockIdx.x] = (double)a;
        __threadfence();
        unsigned prev = atomicAdd(&g_sync, 1u);
        isLast = (prev == (unsigned)(kBlocks - 1));
    }
    __syncthreads();

    // ---- last block: fixed-order final sum => deterministic ----
    if (isLast) {
        __threadfence();
        double a = 0.0;
#pragma unroll
        for (int j = 0; j < kBlocks / kThreads; j++)
            a += g_partials[tid + j * kThreads];
        sa[tid] = a;
        __syncthreads();
        for (int off = kThreads / 2; off > 0; off >>= 1) {
            if (tid < off) sa[tid] += sa[tid + off];
            __syncthreads();
        }
        if (tid == 0) {
            // loss = W*HUBER^2 * S / (64*2043*3);  s32 pre-scaled by kC32
            out[0] = (float)(25.0 * sa[0] / 392256.0);
            g_sync = 0;                          // reset for next graph replay
        }
    }
}

extern "C" void kernel_launch(void* const* d_in, const int* in_sizes, int n_in,
                              void* d_out, int out_size) {
    const float* w_hat = (const float*)d_in[0];
    const float* dw16  = (const float*)d_in[1];
    float* out = (float*)d_out;
    dg_loss_kernel<<<kBlocks, kThreads>>>(w_hat, dw16, out);
}

// round 14
// speedup vs baseline: 1.0440x; 1.0130x over previous
#include <cuda_runtime.h>

namespace {
constexpr int kGroups   = 131072;                 // 64 * 2048
constexpr int kThreadsT = 2 * kGroups;            // 2 threads (halves) per group
constexpr int kThreads  = 256;
constexpr int kBlocks   = kThreadsT / kThreads;   // 1024
constexpr int kVecs     = kThreads * 6;           // 1536 float4 per block tile
constexpr int kTileBytes = kVecs * 16;            // 24576
constexpr float kDT  = 0.005f;
constexpr float kC32 = (float)(392256.0 / 782592.0);  // fold loss32 denom into lane weight
}

__device__ double g_partials[kBlocks];
__device__ unsigned int g_sync = 0;

__device__ __forceinline__ unsigned smem_u32(const void* p) {
    unsigned a;
    asm("{ .reg .u64 t; cvta.to.shared.u64 t, %1; cvt.u32.u64 %0, t; }"
        : "=r"(a) : "l"(p));
    return a;
}

// 16B load with 64B L2 fetch granularity (default policy fetches 128B -> 2x waste)
__device__ __forceinline__ float4 ldg_v4_64B(const float4* p) {
    float4 v;
    asm("ld.global.L2::64B.v4.f32 {%0, %1, %2, %3}, [%4];"
        : "=f"(v.x), "=f"(v.y), "=f"(v.z), "=f"(v.w) : "l"(p));
    return v;
}

__device__ __forceinline__ void qmul(float aw, float ax, float ay, float az,
                                     float bw, float bx, float by, float bz,
                                     float& w, float& x, float& y, float& z) {
    w = aw*bw - ax*bx - ay*by - az*bz;
    x = aw*bx + ax*bw + ay*bz - az*by;
    y = aw*by - ax*bz + ay*bw + az*bx;
    z = aw*bz + ax*by - ay*bx + az*bw;
}

// exp of phi = kDT * u as unit quaternion, |phi| <= ~0.2: even-poly, branch-free.
__device__ __forceinline__ void exp_quat_dt(float ux, float uy, float uz,
                                            float& w, float& x, float& y, float& z) {
    float n2 = fmaf(ux, ux, fmaf(uy, uy, uz * uz));
    float h2 = (0.25f * kDT * kDT) * n2;                    // (|phi|/2)^2
    w = fmaf(h2, fmaf(h2, (1.0f / 24.0f), -0.5f), 1.0f);
    float s = fmaf(h2, fmaf(h2, (kDT / 240.0f), -(kDT / 12.0f)), 0.5f * kDT);
    x = s * ux; y = s * uy; z = s * uz;                     // s = sin(h)/|u|
}

// atan2(n, w) for n >= 0, w >= 0 (result in [0, pi/2]); ~1e-7 rad
__device__ __forceinline__ float atan2_pos(float n, float w) {
    bool swap = n > w;
    float num = swap ? w : n;
    float den = swap ? n : w;
    float q  = __fdividef(num, den);              // [0, 1]
    float q2 = q * q;
    float p =                     -0.0040540580734172f;
    p = fmaf(p, q2,  0.0218612288251226f);
    p = fmaf(p, q2, -0.0559098861838105f);
    p = fmaf(p, q2,  0.0964200441046623f);
    p = fmaf(p, q2, -0.1390853351676372f);
    p = fmaf(p, q2,  0.1994653599057577f);
    p = fmaf(p, q2, -0.3332985605689738f);
    p = fmaf(p, q2,  0.9999993329093277f);
    float a = p * q;
    return swap ? (1.5707963267948966f - a) : a;
}

// rs = log( R(a)^T R(b) );  returns sum_k SmoothL1(rs_k / HUBER)
__device__ __forceinline__ float log_huber_q(float aw, float ax, float ay, float az,
                                             float bw, float bx, float by, float bz) {
    float w = aw*bw + ax*bx + ay*by + az*bz;      // conj(a) (x) b
    float x = aw*bx - ax*bw - ay*bz + az*by;
    float y = aw*by + ax*bz - ay*bw - az*bx;
    float z = aw*bz - ax*by + ay*bx - az*bw;
    if (w < 0.0f) { w = -w; x = -x; y = -y; z = -z; }
    float n2 = fmaf(x, x, fmaf(y, y, z * z));
    float n  = sqrtf(n2);
    float ang = 2.0f * atan2_pos(n, w);           // [0, pi]
    float coef = __fdividef(ang, fmaxf(n, 1e-20f));
    float r0 = coef * x, r1 = coef * y, r2 = coef * z;

    float sum = 0.0f;
#pragma unroll
    for (int k = 0; k < 3; k++) {
        float r = (k == 0) ? r0 : ((k == 1) ? r1 : r2);
        float xx = r * 200.0f;                    // / HUBER
        float axv = fabsf(xx);
        sum += (axv < 1.0f) ? (0.5f * xx * xx) : (axv - 0.5f);
    }
    return sum;
}

__global__ void __launch_bounds__(kThreads, 8)
dg_loss_kernel(const float* __restrict__ w_hat, const float* __restrict__ dw16,
               float* __restrict__ out) {
    __shared__ alignas(128) float4 tile[kVecs];   // 24 KB raw w_hat tile
    __shared__ alignas(8) unsigned long long mbar;

    const int tid  = threadIdx.x;
    const int t    = blockIdx.x * kThreads + tid;          // half-group id
    const int m    = t >> 1;                               // group id
    const int g    = m & 2047;                             // group index in row
    const int half = t & 1;
    const int lane = tid & 31;
    const bool mEven = (m & 1) == 0;

    // ---- TMA bulk load of the whole w_hat tile: bypasses L1tex ----
    const unsigned mb = smem_u32(&mbar);
    if (tid == 0) {
        asm volatile("mbarrier.init.shared.b64 [%0], %1;" :: "r"(mb), "r"(1) : "memory");
    }
    __syncthreads();
    if (tid == 0) {
        asm volatile("mbarrier.arrive.expect_tx.shared.b64 _, [%0], %1;"
                     :: "r"(mb), "r"((unsigned)kTileBytes) : "memory");
        const char* src = reinterpret_cast<const char*>(w_hat)
                        + (size_t)blockIdx.x * kTileBytes;
        asm volatile("cp.async.bulk.shared::cta.global.mbarrier::complete_tx::bytes "
                     "[%0], [%1], %2, [%3];"
                     :: "r"(smem_u32(tile)), "l"(src), "r"((unsigned)kTileBytes), "r"(mb)
                     : "memory");
    }

    // ---- overlap with the wait: dw16 (one 64B-granule load per group) + gt exp ----
    float4 d = make_float4(0.f, 0.f, 0.f, 0.f);
    if (half == 0)
        d = ldg_v4_64B(reinterpret_cast<const float4*>(dw16) + (size_t)m * 12);
    {
        int src = lane & ~1;                               // even lane of the pair
        d.x = __shfl_sync(0xFFFFFFFFu, d.x, src);
        d.y = __shfl_sync(0xFFFFFFFFu, d.y, src);
        d.z = __shfl_sync(0xFFFFFFFFu, d.z, src);
    }
    float pw, px, py, pz;
    {
        float n2 = fmaf(d.x, d.x, fmaf(d.y, d.y, d.z * d.z));
        float th = sqrtf(n2);
        float s, c;
        __sincosf(0.5f * th, &s, &c);
        float k = (th > 1e-7f) ? __fdividef(s, th) : 0.5f;
        pw = c; px = k * d.x; py = k * d.y; pz = k * d.z;
    }

    // ---- wait for the bulk copy (acquire: orders subsequent ld.shared) ----
    {
        unsigned done;
        asm volatile(
            "{\n\t.reg .pred p;\n\t"
            "mbarrier.try_wait.parity.acquire.cta.shared::cta.b64 p, [%1], %2;\n\t"
            "selp.b32 %0, 1, 0, p;\n\t}"
            : "=r"(done) : "r"(mb), "r"(0u) : "memory");
        if (!done) {
            asm volatile(
                "{\n\t.reg .pred P1;\n\t"
                "WL_%=:\n\t"
                "mbarrier.try_wait.parity.acquire.cta.shared::cta.b64 P1, [%0], %1, 0x989680;\n\t"
                "@P1 bra.uni WD_%=;\n\t"
                "bra.uni WL_%=;\n\t"
                "WD_%=:\n\t}"
                :: "r"(mb), "r"(0u) : "memory");
        }
    }

    // ---- phase 2: sum this half-group's 24 floats (BCH); component = i % 3 ----
    float ux, uy, uz;
    {
        const float4* p = tile + 6 * tid;
        float4 q0 = p[0], q1 = p[1], q2 = p[2], q3 = p[3], q4 = p[4], q5 = p[5];
        ux = ((q0.x + q0.w) + (q1.z + q2.y)) + ((q3.x + q3.w) + (q4.z + q5.y));
        uy = ((q0.y + q1.x) + (q1.w + q2.z)) + ((q3.y + q4.x) + (q4.w + q5.z));
        uz = ((q0.z + q1.y) + (q2.x + q2.w)) + ((q3.z + q4.y) + (q5.x + q5.w));
    }

    // ---- combine halves (BCH: vector sums add); both lanes identical ----
    ux += __shfl_xor_sync(0xFFFFFFFFu, ux, 1);
    uy += __shfl_xor_sync(0xFFFFFFFFu, uy, 1);
    uz += __shfl_xor_sync(0xFFFFFFFFu, uz, 1);

    float qw, qx, qy, qz;
    exp_quat_dt(ux, uy, uz, qw, qx, qy, qz);      // qhat for group m

    // ---- exchange with partner group (m ^ 1): lanes t <-> t^2 ----
    float qwP = __shfl_xor_sync(0xFFFFFFFFu, qw, 2);
    float qxP = __shfl_xor_sync(0xFFFFFFFFu, qx, 2);
    float qyP = __shfl_xor_sync(0xFFFFFFFFu, qy, 2);
    float qzP = __shfl_xor_sync(0xFFFFFFFFu, qz, 2);
    float pwP = __shfl_xor_sync(0xFFFFFFFFu, pw, 2);
    float pxP = __shfl_xor_sync(0xFFFFFFFFu, px, 2);
    float pyP = __shfl_xor_sync(0xFFFFFFFFu, py, 2);
    float pzP = __shfl_xor_sync(0xFFFFFFFFu, pz, 2);

    // ---- branch-free lane specialization: partner or identity (exact) ----
    bool pair = (half == 1);
    float sw = pair ? qwP : 1.0f, sx = pair ? qxP : 0.0f,
          sy = pair ? qyP : 0.0f, sz = pair ? qzP : 0.0f;
    float tw = pair ? pwP : 1.0f, tx = pair ? pxP : 0.0f,
          ty = pair ? pyP : 0.0f, tz = pair ? pzP : 0.0f;
    float Aw, Ax, Ay, Az, Bw, Bx, By, Bz;
    qmul(qw, qx, qy, qz, sw, sx, sy, sz, Aw, Ax, Ay, Az);
    qmul(pw, px, py, pz, tw, tx, ty, tz, Bw, Bx, By, Bz);

    float val = log_huber_q(Aw, Ax, Ay, Az, Bw, Bx, By, Bz);

    bool valid = pair ? (mEven && g >= 10) : (g >= 5);
    float v = valid ? (pair ? val * kC32 : val) : 0.0f;

    // ---- deterministic block reduction ----
#pragma unroll
    for (int off = 16; off > 0; off >>= 1)
        v += __shfl_down_sync(0xFFFFFFFFu, v, off);
    __shared__ float warr[kThreads / 32];
    __shared__ double sa[kThreads];
    __shared__ bool isLast;
    int wid = tid >> 5;
    if (lane == 0) warr[wid] = v;
    __syncthreads();
    if (tid == 0) {
        float a = 0.0f;
#pragma unroll
        for (int i = 0; i < kThreads / 32; i++) a += warr[i];
        g_partials[blockIdx.x] = (double)a;
        __threadfence();
        unsigned prev = atomicAdd(&g_sync, 1u);
        isLast = (prev == (unsigned)(kBlocks - 1));
    }
    __syncthreads();

    // ---- last block: fixed-order final sum => deterministic ----
    if (isLast) {
        __threadfence();
        double a = 0.0;
#pragma unroll
        for (int j = 0; j < kBlocks / kThreads; j++)
            a += g_partials[tid + j * kThreads];
        sa[tid] = a;
        __syncthreads();
        for (int off = kThreads / 2; off > 0; off >>= 1) {
            if (tid < off) sa[tid] += sa[tid + off];
            __syncthreads();
        }
        if (tid == 0) {
            // loss = W*HUBER^2 * S / (64*2043*3);  s32 pre-scaled by kC32
            out[0] = (float)(25.0 * sa[0] / 392256.0);
            g_sync = 0;                          // reset for next graph replay
        }
    }
}

extern "C" void kernel_launch(void* const* d_in, const int* in_sizes, int n_in,
                              void* d_out, int out_size) {
    const float* w_hat = (const float*)d_in[0];
    const float* dw16  = (const float*)d_in[1];
    float* out = (float*)d_out;
    dg_loss_kernel<<<kBlocks, kThreads>>>(w_hat, dw16, out);
}